// round 17
// baseline (speedup 1.0000x reference)
#include <cuda_runtime.h>
#include <cuda_fp16.h>
#include <math.h>
#include <stdint.h>

#define B    64
#define T    2048
#define D    128
#define H    256
#define G4   1024
#define OUTN 64
#define MROWS (T * B)
#define NB_L0 64
#define NB_L1 64
#define NBLK  (NB_L0 + NB_L1)
#define RING 8

typedef unsigned long long ull;

// lstm dynamic SMEM layout (bytes)
#define OFF_B   66560
#define OFF_RED 83200
#define SMEM_BYTES 87552

// ---------------- scratch ------------------------------------------------------
__device__ __half g_eh[(size_t)MROWS * D];          // [m][d] fp16
__device__ float  g_xg0[(size_t)MROWS * G4];        // [m][col] (includes bias0)
__device__ __half g_h1all[(size_t)MROWS * H];       // [m][k] fp16
__device__ __half g_h0buf[RING][B * H];             // [ring][b][k]
__device__ __half g_h1buf[RING][B * H];
__device__ float  g_bias0[G4];
__device__ float  g_bias1[G4];
__device__ int    g_flag0[4][32];                   // [bg][jg] = step+1 (128B rows)
__device__ int    g_flag1[4][32];

__device__ __forceinline__ float tanha(float x) {
    float r;
    asm("tanh.approx.f32 %0, %1;" : "=f"(r) : "f"(x));
    return r;
}
__device__ __forceinline__ float sigf(float x) { return 0.5f * tanha(0.5f * x) + 0.5f; }

// poll 16 single-writer flags until all >= thr (loads pipeline: ~1 L2 round trip)
__device__ __forceinline__ void wait_flags16(const int* f, int thr) {
    bool ok;
    do {
        ok = true;
#pragma unroll
        for (int i = 0; i < 16; i++) {
            int v;
            asm volatile("ld.global.acquire.gpu.b32 %0, [%1];"
                         : "=r"(v) : "l"(f + i) : "memory");
            ok &= (v >= thr);
        }
    } while (!ok);
}
__device__ __forceinline__ void flag_rel(int* p, int v) {
    asm volatile("st.release.gpu.global.b32 [%0], %1;" :: "l"(p), "r"(v) : "memory");
}

// ---------------- warp MMA helpers -----------------------------------------------
__device__ __forceinline__ uint32_t smem_u32(const void* p) {
    uint32_t a;
    asm("{ .reg .u64 t; cvta.to.shared.u64 t, %1; cvt.u32.u64 %0, t; }" : "=r"(a) : "l"(p));
    return a;
}
__device__ __forceinline__ void ldsm_x4(uint32_t& a0, uint32_t& a1, uint32_t& a2,
                                        uint32_t& a3, uint32_t addr) {
    asm volatile("ldmatrix.sync.aligned.m8n8.x4.shared.b16 {%0,%1,%2,%3}, [%4];"
                 : "=r"(a0), "=r"(a1), "=r"(a2), "=r"(a3) : "r"(addr));
}
__device__ __forceinline__ void ldsm_x2(uint32_t& b0, uint32_t& b1, uint32_t addr) {
    asm volatile("ldmatrix.sync.aligned.m8n8.x2.shared.b16 {%0,%1}, [%2];"
                 : "=r"(b0), "=r"(b1) : "r"(addr));
}
__device__ __forceinline__ void mma16816(float* d, uint32_t a0, uint32_t a1,
                                         uint32_t a2, uint32_t a3,
                                         uint32_t b0, uint32_t b1) {
    asm volatile(
        "mma.sync.aligned.m16n8k16.row.col.f32.f16.f16.f32 "
        "{%0,%1,%2,%3}, {%4,%5,%6,%7}, {%8,%9}, {%0,%1,%2,%3};"
        : "+f"(d[0]), "+f"(d[1]), "+f"(d[2]), "+f"(d[3])
        : "r"(a0), "r"(a1), "r"(a2), "r"(a3), "r"(b0), "r"(b1));
}

// ---------------- tiny kernels -----------------------------------------------------
__global__ void prep_bias(const float* __restrict__ bih0, const float* __restrict__ bhh0,
                          const float* __restrict__ bih1, const float* __restrict__ bhh1) {
    int i = blockIdx.x * 256 + threadIdx.x;
    if (i < G4) {
        g_bias0[i] = bih0[i] + bhh0[i];
        g_bias1[i] = bih1[i] + bhh1[i];
    }
}

__global__ void embed_kernel(const int* __restrict__ x, const float* __restrict__ table) {
    size_t idx = ((size_t)blockIdx.x * 256 + threadIdx.x) * 2;
    int d = (int)(idx & (D - 1));
    size_t m = idx >> 7;
    int t = (int)(m >> 6);
    int b = (int)(m & 63);
    int xi = __ldg(&x[(size_t)b * T + t]);
    __half2 v;
    if (xi == 0) {
        v = __floats2half2_rn(0.f, 0.f);
    } else {
        const float* src = &table[(size_t)xi * D + d];
        v = __floats2half2_rn(src[0], src[1]);
    }
    *(__half2*)&g_eh[idx] = v;
}

// ------- xg0 = e @ Wih0^T + bias0 via HMMA; M=131072, N(gates)=1024, K=128 ---------
#define XS 72
__global__ void __launch_bounds__(256, 2) gemm_xg0(const float* __restrict__ Wih) {
    __shared__ __half As[128 * XS];
    __shared__ __half Bs[64 * XS];
    const int tid = threadIdx.x;
    const int warp = tid >> 5, lane = tid & 31;
    const size_t m0 = (size_t)blockIdx.y * 128;
    const int    n0 = blockIdx.x * 64;

    const int wm = (warp & 3) * 32;
    const int wn = (warp >> 2) * 32;

    float d[2][4][4];
#pragma unroll
    for (int mt = 0; mt < 2; mt++)
#pragma unroll
        for (int nt = 0; nt < 4; nt++)
#pragma unroll
            for (int i = 0; i < 4; i++) d[mt][nt][i] = 0.f;

    const uint32_t sA = smem_u32(As), sB = smem_u32(Bs);
    const uint32_t aA0 = sA + 2u * (uint32_t)((wm + (lane & 15)) * XS + ((lane >> 4) << 3));
    const uint32_t aA1 = aA0 + 2u * 16 * XS;
    const uint32_t aB0 = sB + 2u * (uint32_t)((wn + (lane & 7) + ((lane >> 4) << 3)) * XS
                                              + (((lane >> 3) & 1) << 3));
    const uint32_t aB1 = aB0 + 2u * 16 * XS;

    for (int kc = 0; kc < 2; kc++) {
        for (int i = tid; i < 128 * 8; i += 256) {
            int r = i >> 3, u = i & 7;
            *(uint4*)&As[r * XS + u * 8] =
                *(const uint4*)&g_eh[(m0 + r) * D + kc * 64 + u * 8];
        }
        for (int i = tid; i < 1024; i += 256) {
            int r = i >> 4, u = i & 15;
            float4 w = *(const float4*)&Wih[(size_t)(n0 + r) * D + kc * 64 + u * 4];
            __half2* dst = (__half2*)&Bs[r * XS + u * 4];
            dst[0] = __floats2half2_rn(w.x, w.y);
            dst[1] = __floats2half2_rn(w.z, w.w);
        }
        __syncthreads();
#pragma unroll
        for (int kk = 0; kk < 4; kk++) {
            uint32_t a0[4], a1[4], b0[4], b1[4];
            ldsm_x4(a0[0], a0[1], a0[2], a0[3], aA0 + kk * 32);
            ldsm_x4(a1[0], a1[1], a1[2], a1[3], aA1 + kk * 32);
            ldsm_x4(b0[0], b0[1], b0[2], b0[3], aB0 + kk * 32);
            ldsm_x4(b1[0], b1[1], b1[2], b1[3], aB1 + kk * 32);
#pragma unroll
            for (int nt = 0; nt < 2; nt++) {
                mma16816(d[0][nt],     a0[0], a0[1], a0[2], a0[3], b0[nt * 2], b0[nt * 2 + 1]);
                mma16816(d[1][nt],     a1[0], a1[1], a1[2], a1[3], b0[nt * 2], b0[nt * 2 + 1]);
                mma16816(d[0][nt + 2], a0[0], a0[1], a0[2], a0[3], b1[nt * 2], b1[nt * 2 + 1]);
                mma16816(d[1][nt + 2], a1[0], a1[1], a1[2], a1[3], b1[nt * 2], b1[nt * 2 + 1]);
            }
        }
        __syncthreads();
    }
    const int rowq = lane >> 2, c2 = (lane & 3) * 2;
#pragma unroll
    for (int mt = 0; mt < 2; mt++) {
#pragma unroll
        for (int nt = 0; nt < 4; nt++) {
            int gc = n0 + wn + nt * 8 + c2;
            float bv0 = g_bias0[gc], bv1 = g_bias0[gc + 1];
            size_t gr = m0 + wm + mt * 16 + rowq;
            float2 v0 = make_float2(d[mt][nt][0] + bv0, d[mt][nt][1] + bv1);
            float2 v1 = make_float2(d[mt][nt][2] + bv0, d[mt][nt][3] + bv1);
            *(float2*)&g_xg0[gr * G4 + gc]       = v0;
            *(float2*)&g_xg0[(gr + 8) * G4 + gc] = v1;
        }
    }
}

// ---------------- persistent HMMA 2-layer LSTM (R15 structure, flag sync) -----------
extern __shared__ __align__(1024) char smem_raw[];

__global__ void __launch_bounds__(256, 1) lstm_kernel(
    const float* __restrict__ Whh0,
    const float* __restrict__ Wih1,
    const float* __restrict__ Whh1)
{
    float* red = (float*)(smem_raw + OFF_RED);   // [64][17]
    const uint32_t sbase = smem_u32(smem_raw);
    const int bid = blockIdx.x, tid = threadIdx.x;
    const int warp = tid >> 5, lane = tid & 31;

    const bool isL0 = bid < NB_L0;
    const int lb = isL0 ? bid : bid - NB_L0;
    const int jg = lb >> 2, bg = lb & 3;
    const int j0 = jg * 16, b0 = bg * 16;
    const int K  = isL0 ? 256 : 512;
    const int SA = isL0 ? 264 : 520;

    {
        __half* A_s = (__half*)smem_raw;
        for (int i = tid; i < 64 * K; i += 256) {
            int r = i / K, k = i - r * K;
            int grow = (r >> 4) * 256 + j0 + (r & 15);
            float w;
            if (isL0)          w = Whh0[(size_t)grow * H + k];
            else if (k < 256)  w = Wih1[(size_t)grow * H + k];
            else               w = Whh1[(size_t)grow * H + (k - 256)];
            A_s[r * SA + k] = __float2half_rn(w);
        }
    }

    const int r0 = (warp & 3) * 16, n0w = (warp >> 2) * 8;
    const uint32_t aA = sbase + 2u * (uint32_t)((r0 + (lane & 15)) * SA + ((lane >> 4) << 3));
    const int blane = lane & 15;
    const uint32_t aB = sbase + OFF_B +
        2u * (uint32_t)(((n0w + (blane & 7)) * SA) + (((blane >> 3) & 1) << 3));

    const int jj = tid & 15, bl = tid >> 4;
    float c_reg = 0.f;
    float bi[4];
    if (!isL0) {
#pragma unroll
        for (int g = 0; g < 4; g++) bi[g] = g_bias1[g * 256 + j0 + jj];
    }
    __syncthreads();

    const uint32_t SBb = 2u * (uint32_t)SA;

    if (isL0) {
        // ===================== layer 0 =====================
        for (int t = 0; t < T; ++t) {
            float xp[4];
            {
                const float* xg = g_xg0 + ((size_t)t * B + b0 + bl) * G4 + j0 + jj;
#pragma unroll
                for (int g = 0; g < 4; g++) xp[g] = xg[g * 256];
            }

            if (t >= 1)    wait_flags16(&g_flag0[bg][0], t);           // h0[t-1] ready
            if (t >= RING) wait_flags16(&g_flag1[bg][0], t - RING + 1); // WAR guard

            char* smB = smem_raw + OFF_B;
            const __half* hsrc = g_h0buf[(t + RING - 1) & (RING - 1)];
#pragma unroll
            for (int rep = 0; rep < 2; rep++) {
                int c = rep * 256 + tid;
                int n = c >> 5, u = c & 31;
                uint4 v = *(const uint4*)(hsrc + (size_t)(b0 + n) * 256 + u * 8);
                *(uint4*)(smB + n * SBb + u * 16) = v;
            }
            __syncthreads();

            float d[4] = {0.f, 0.f, 0.f, 0.f};
#pragma unroll 8
            for (int kk = 0; kk < 16; kk++) {
                uint32_t a0, a1, a2, a3, bb0, bb1;
                ldsm_x4(a0, a1, a2, a3, aA + kk * 32);
                ldsm_x2(bb0, bb1, aB + kk * 32);
                mma16816(d, a0, a1, a2, a3, bb0, bb1);
            }
            {
                int row = r0 + (lane >> 2);
                int col = n0w + (lane & 3) * 2;
                red[row * 17 + col]           = d[0];
                red[row * 17 + col + 1]       = d[1];
                red[(row + 8) * 17 + col]     = d[2];
                red[(row + 8) * 17 + col + 1] = d[3];
            }
            __syncthreads();

            {
                float s0 = xp[0] + red[(jj)      * 17 + bl];
                float s1 = xp[1] + red[(16 + jj) * 17 + bl];
                float s2 = xp[2] + red[(32 + jj) * 17 + bl];
                float s3 = xp[3] + red[(48 + jj) * 17 + bl];
                c_reg = sigf(s1) * c_reg + sigf(s0) * tanha(s2);
                float hval = sigf(s3) * tanha(c_reg);
                g_h0buf[t & (RING - 1)][(size_t)(b0 + bl) * 256 + j0 + jj] =
                    __float2half_rn(hval);
            }
            __syncthreads();
            if (tid == 0) flag_rel(&g_flag0[bg][jg], t + 1);
        }
    } else {
        // ===================== layer 1 (h0 part FIRST, h1 part second) =========
        for (int tp = 0; tp < T; ++tp) {
            char* smB = smem_raw + OFF_B;

            // ---- phase 1: h0(tp) contribution (wait usually non-binding) ----
            wait_flags16(&g_flag0[bg][0], tp + 1);
            {
                const __half* h0s = g_h0buf[tp & (RING - 1)];
#pragma unroll
                for (int rep = 0; rep < 2; rep++) {
                    int c = rep * 256 + tid;
                    int n = c >> 5, u = c & 31;
                    uint4 v = *(const uint4*)(h0s + (size_t)(b0 + n) * 256 + u * 8);
                    *(uint4*)(smB + n * SBb + u * 16) = v;   // cols 0..255
                }
            }
            __syncthreads();

            float d[4] = {0.f, 0.f, 0.f, 0.f};
#pragma unroll 8
            for (int kk = 0; kk < 16; kk++) {
                uint32_t a0, a1, a2, a3, bb0, bb1;
                ldsm_x4(a0, a1, a2, a3, aA + kk * 32);
                ldsm_x2(bb0, bb1, aB + kk * 32);
                mma16816(d, a0, a1, a2, a3, bb0, bb1);
            }

            // ---- phase 2: h1(tp-1) contribution (the real dependency) ----
            if (tp >= 1) wait_flags16(&g_flag1[bg][0], tp);
            {
                const __half* h1s = g_h1buf[(tp + RING - 1) & (RING - 1)];
#pragma unroll
                for (int rep = 0; rep < 2; rep++) {
                    int c = rep * 256 + tid;
                    int n = c >> 5, u = c & 31;
                    uint4 v = *(const uint4*)(h1s + (size_t)(b0 + n) * 256 + u * 8);
                    *(uint4*)(smB + n * SBb + 512 + u * 16) = v;   // cols 256..511
                }
            }
            __syncthreads();

#pragma unroll 8
            for (int kk = 16; kk < 32; kk++) {
                uint32_t a0, a1, a2, a3, bb0, bb1;
                ldsm_x4(a0, a1, a2, a3, aA + kk * 32);
                ldsm_x2(bb0, bb1, aB + kk * 32);
                mma16816(d, a0, a1, a2, a3, bb0, bb1);
            }
            {
                int row = r0 + (lane >> 2);
                int col = n0w + (lane & 3) * 2;
                red[row * 17 + col]           = d[0];
                red[row * 17 + col + 1]       = d[1];
                red[(row + 8) * 17 + col]     = d[2];
                red[(row + 8) * 17 + col + 1] = d[3];
            }
            __syncthreads();

            float hval;
            {
                float s0 = bi[0] + red[(jj)      * 17 + bl];
                float s1 = bi[1] + red[(16 + jj) * 17 + bl];
                float s2 = bi[2] + red[(32 + jj) * 17 + bl];
                float s3 = bi[3] + red[(48 + jj) * 17 + bl];
                c_reg = sigf(s1) * c_reg + sigf(s0) * tanha(s2);
                hval = sigf(s3) * tanha(c_reg);
                g_h1buf[tp & (RING - 1)][(size_t)(b0 + bl) * 256 + j0 + jj] =
                    __float2half_rn(hval);
            }
            __syncthreads();
            if (tid == 0) flag_rel(&g_flag1[bg][jg], tp + 1);
            // off critical path: archive h1 for the FC (kernel-ordered consumer)
            g_h1all[((size_t)tp * B + b0 + bl) * H + j0 + jj] = __float2half_rn(hval);
        }
    }
}

// ------- FC + fused softmax: out[b][t][o] = softmax(h1 @ fcW^T + fcb) ---------------
__global__ void __launch_bounds__(256, 2) gemm_fc(const float* __restrict__ fcW,
                                                  const float* __restrict__ fcb,
                                                  float* __restrict__ out) {
    __shared__ __align__(16) char fcsm[128 * 68 * 4];   // As+Bs then logits tile
    __half* As = (__half*)fcsm;                          // 128*XS halves = 18432 B
    __half* Bs = (__half*)(fcsm + 128 * XS * 2);         // 64*XS halves  =  9216 B
    float*  Ls = (float*)fcsm;                           // [128][68] after MMA
    const int tid = threadIdx.x;
    const int warp = tid >> 5, lane = tid & 31;
    const size_t m0 = (size_t)blockIdx.x * 128;

    const int wm = (warp & 3) * 32;
    const int wn = (warp >> 2) * 32;

    float d[2][4][4];
#pragma unroll
    for (int mt = 0; mt < 2; mt++)
#pragma unroll
        for (int nt = 0; nt < 4; nt++)
#pragma unroll
            for (int i = 0; i < 4; i++) d[mt][nt][i] = 0.f;

    const uint32_t sA = smem_u32(As), sB = smem_u32(Bs);
    const uint32_t aA0 = sA + 2u * (uint32_t)((wm + (lane & 15)) * XS + ((lane >> 4) << 3));
    const uint32_t aA1 = aA0 + 2u * 16 * XS;
    const uint32_t aB0 = sB + 2u * (uint32_t)((wn + (lane & 7) + ((lane >> 4) << 3)) * XS
                                              + (((lane >> 3) & 1) << 3));
    const uint32_t aB1 = aB0 + 2u * 16 * XS;

    for (int kc = 0; kc < 4; kc++) {
        for (int i = tid; i < 128 * 8; i += 256) {
            int r = i >> 3, u = i & 7;
            *(uint4*)&As[r * XS + u * 8] =
                *(const uint4*)&g_h1all[(m0 + r) * H + kc * 64 + u * 8];
        }
        for (int i = tid; i < 1024; i += 256) {
            int r = i >> 4, u = i & 15;
            float4 w = *(const float4*)&fcW[(size_t)r * H + kc * 64 + u * 4];
            __half2* dst = (__half2*)&Bs[r * XS + u * 4];
            dst[0] = __floats2half2_rn(w.x, w.y);
            dst[1] = __floats2half2_rn(w.z, w.w);
        }
        __syncthreads();
#pragma unroll
        for (int kk = 0; kk < 4; kk++) {
            uint32_t a0[4], a1[4], b0[4], b1[4];
            ldsm_x4(a0[0], a0[1], a0[2], a0[3], aA0 + kk * 32);
            ldsm_x4(a1[0], a1[1], a1[2], a1[3], aA1 + kk * 32);
            ldsm_x4(b0[0], b0[1], b0[2], b0[3], aB0 + kk * 32);
            ldsm_x4(b1[0], b1[1], b1[2], b1[3], aB1 + kk * 32);
#pragma unroll
            for (int nt = 0; nt < 2; nt++) {
                mma16816(d[0][nt],     a0[0], a0[1], a0[2], a0[3], b0[nt * 2], b0[nt * 2 + 1]);
                mma16816(d[1][nt],     a1[0], a1[1], a1[2], a1[3], b0[nt * 2], b0[nt * 2 + 1]);
                mma16816(d[0][nt + 2], a0[0], a0[1], a0[2], a0[3], b1[nt * 2], b1[nt * 2 + 1]);
                mma16816(d[1][nt + 2], a1[0], a1[1], a1[2], a1[3], b1[nt * 2], b1[nt * 2 + 1]);
            }
        }
        __syncthreads();
    }
    // write logits tile to SMEM (As/Bs dead now)
    const int rowq = lane >> 2, c2 = (lane & 3) * 2;
#pragma unroll
    for (int mt = 0; mt < 2; mt++) {
#pragma unroll
        for (int nt = 0; nt < 4; nt++) {
            int gc = wn + nt * 8 + c2;
            float bv0 = fcb[gc], bv1 = fcb[gc + 1];
            int lr = wm + mt * 16 + rowq;
            Ls[lr * 68 + gc]           = d[mt][nt][0] + bv0;
            Ls[lr * 68 + gc + 1]       = d[mt][nt][1] + bv1;
            Ls[(lr + 8) * 68 + gc]     = d[mt][nt][2] + bv0;
            Ls[(lr + 8) * 68 + gc + 1] = d[mt][nt][3] + bv1;
        }
    }
    __syncthreads();

    // fused softmax: 2 threads per row (adjacent lanes), 32 cols each
    {
        const int row = tid >> 1, half = tid & 1;
        const float* Lr = Ls + row * 68 + half * 32;
        float v[32];
#pragma unroll
        for (int i = 0; i < 32; i++) v[i] = Lr[i];
        float mx = v[0];
#pragma unroll
        for (int i = 1; i < 32; i++) mx = fmaxf(mx, v[i]);
        mx = fmaxf(mx, __shfl_xor_sync(~0u, mx, 1));
        float s = 0.f;
#pragma unroll
        for (int i = 0; i < 32; i++) { v[i] = __expf(v[i] - mx); s += v[i]; }
        s += __shfl_xor_sync(~0u, s, 1);
        float inv = 1.f / s;
        size_t m = m0 + row;
        int t = (int)(m >> 6), b = (int)(m & 63);
        float* O = out + ((size_t)b * T + t) * OUTN + half * 32;
#pragma unroll
        for (int i = 0; i < 32; i += 4) {
            float4 q = make_float4(v[i] * inv, v[i + 1] * inv, v[i + 2] * inv, v[i + 3] * inv);
            *(float4*)(O + i) = q;
        }
    }
}

// ---------------- launch -------------------------------------------------------------
extern "C" void kernel_launch(void* const* d_in, const int* in_sizes, int n_in,
                              void* d_out, int out_size) {
    const int*   x     = (const int*)d_in[0];
    const float* table = (const float*)d_in[1];
    const float* Wih0  = (const float*)d_in[2];
    const float* Whh0  = (const float*)d_in[3];
    const float* bih0  = (const float*)d_in[4];
    const float* bhh0  = (const float*)d_in[5];
    const float* Wih1  = (const float*)d_in[6];
    const float* Whh1  = (const float*)d_in[7];
    const float* bih1  = (const float*)d_in[8];
    const float* bhh1  = (const float*)d_in[9];
    const float* fcW   = (const float*)d_in[10];
    const float* fcb   = (const float*)d_in[11];
    float* out = (float*)d_out;

    cudaFuncSetAttribute(lstm_kernel,
                         cudaFuncAttributeMaxDynamicSharedMemorySize, SMEM_BYTES);

    void *p0, *p1, *ph0, *ph1;
    cudaGetSymbolAddress(&p0,  g_flag0);
    cudaGetSymbolAddress(&p1,  g_flag1);
    cudaGetSymbolAddress(&ph0, g_h0buf);
    cudaGetSymbolAddress(&ph1, g_h1buf);
    cudaMemsetAsync(p0,  0, 4 * 32 * sizeof(int));
    cudaMemsetAsync(p1,  0, 4 * 32 * sizeof(int));
    cudaMemsetAsync(ph0, 0, RING * B * H * sizeof(__half));
    cudaMemsetAsync(ph1, 0, RING * B * H * sizeof(__half));

    prep_bias<<<4, 256>>>(bih0, bhh0, bih1, bhh1);
    embed_kernel<<<(MROWS * D) / 512, 256>>>(x, table);
    gemm_xg0<<<dim3(G4 / 64, MROWS / 128), 256>>>(Wih0);

    lstm_kernel<<<NBLK, 256, SMEM_BYTES>>>(Whh0, Wih1, Whh1);

    gemm_fc<<<MROWS / 128, 256>>>(fcW, fcb, out);
}